// round 15
// baseline (speedup 1.0000x reference)
#include <cuda_runtime.h>
#include <cuda_bf16.h>
#include <cstdint>

#define H 64
#define V 128
#define S 64
#define BATCH 256
#define L 4096

typedef unsigned long long u64;
typedef unsigned int u32;
typedef unsigned short u16;

// Scratch (no allocs allowed)
__device__ float d_hn[V * H];      // LN'd hidden per vocab id
__device__ float d_gTf[S * V];     // gate softmax, transposed [s][v], fp32
__device__ u64   d_Bfrag[64 * 64]; // [p=vpair][h]: lo32 = bf16x2 hi-parts, hi32 = lo

__device__ __forceinline__ u32 pack_bf16x2(float lo, float hi) {
    u32 d;
    asm("cvt.rn.bf16x2.f32 %0, %1, %2;" : "=r"(d) : "f"(hi), "f"(lo));
    return d;
}
__device__ __forceinline__ float bflo(u32 p) { return __uint_as_float(p << 16); }
__device__ __forceinline__ float bfhi(u32 p) { return __uint_as_float(p & 0xFFFF0000u); }

__device__ __forceinline__ void mma_bf16(float* c, u32 a0, u32 a1, u32 a2, u32 a3,
                                         u32 b0, u32 b1) {
    asm volatile(
        "mma.sync.aligned.m16n8k16.row.col.f32.bf16.bf16.f32 "
        "{%0,%1,%2,%3}, {%4,%5,%6,%7}, {%8,%9}, {%0,%1,%2,%3};"
        : "+f"(c[0]), "+f"(c[1]), "+f"(c[2]), "+f"(c[3])
        : "r"(a0), "r"(a1), "r"(a2), "r"(a3), "r"(b0), "r"(b1));
}

// ---------------------------------------------------------------------------
// Kernel 1: per-vocab precompute ONLY (R13-proven). grid = 128, 128 threads.
// Triggers dependent launch immediately so final can start its histogram.
// ---------------------------------------------------------------------------
__global__ void __launch_bounds__(128) prep_kernel(
        const float* __restrict__ embed_w,
        const float* __restrict__ w1,
        const float* __restrict__ b1,
        const float* __restrict__ w2,
        const float* __restrict__ b2,
        const float* __restrict__ ln_g,
        const float* __restrict__ ln_b,
        const float* __restrict__ gate_w,
        const float* __restrict__ gate_b) {
    cudaTriggerProgrammaticLaunchCompletion();

    int t = threadIdx.x;
    int lane = t & 31;
    int warp = t >> 5;
    int v = blockIdx.x;

    __shared__ float hs[H];
    __shared__ float us[2 * H];
    __shared__ float hns[H];
    __shared__ float wred[2][2];

    if (t < H) hs[t] = embed_w[v * H + t];
    __syncthreads();

    {
        float a0 = b1[t], a1 = 0.0f;
#pragma unroll
        for (int k = 0; k < H; k += 2) {
            a0 = fmaf(hs[k],     w1[k * (2 * H) + t],       a0);
            a1 = fmaf(hs[k + 1], w1[(k + 1) * (2 * H) + t], a1);
        }
        us[t] = fmaxf(a0 + a1, 0.0f);
    }
    __syncthreads();

    float xval = 0.0f;
    if (t < H) {
        float a0 = b2[t], a1 = 0.0f;
#pragma unroll
        for (int k = 0; k < 2 * H; k += 2) {
            a0 = fmaf(us[k],     w2[k * H + t],       a0);
            a1 = fmaf(us[k + 1], w2[(k + 1) * H + t], a1);
        }
        xval = hs[t] + a0 + a1;
        float s = xval, sq = xval * xval;
#pragma unroll
        for (int off = 16; off > 0; off >>= 1) {
            s  += __shfl_xor_sync(0xffffffffu, s, off);
            sq += __shfl_xor_sync(0xffffffffu, sq, off);
        }
        if (lane == 0) { wred[warp][0] = s; wred[warp][1] = sq; }
    }
    __syncthreads();

    if (t < H) {
        float s  = wred[0][0] + wred[1][0];
        float sq = wred[0][1] + wred[1][1];
        float mu = s * (1.0f / H);
        float var = sq * (1.0f / H) - mu * mu;
        float rstd = rsqrtf(var + 1e-5f);
        float val = (xval - mu) * rstd * ln_g[t] + ln_b[t];
        hns[t] = val;
        d_hn[v * H + t] = val;
    }
    __syncthreads();

    float l = 0.0f;
    if (t < S) {
        float a0 = gate_b[t], a1 = 0.0f;
#pragma unroll
        for (int k = 0; k < H; k += 2) {
            a0 = fmaf(hns[k],     gate_w[k * S + t],       a0);
            a1 = fmaf(hns[k + 1], gate_w[(k + 1) * S + t], a1);
        }
        l = a0 + a1;
        float m = l;
#pragma unroll
        for (int off = 16; off > 0; off >>= 1)
            m = fmaxf(m, __shfl_xor_sync(0xffffffffu, m, off));
        if (lane == 0) wred[warp][0] = m;
    }
    __syncthreads();

    float ev = 0.0f;
    if (t < S) {
        float m = fmaxf(wred[0][0], wred[1][0]);
        ev = expf(l - m);
        float ssum = ev;
#pragma unroll
        for (int off = 16; off > 0; off >>= 1)
            ssum += __shfl_xor_sync(0xffffffffu, ssum, off);
        if (lane == 0) wred[warp][1] = ssum;
    }
    __syncthreads();

    if (t < S) {
        d_gTf[t * V + v] = ev / (wred[0][1] + wred[1][1]);
    } else {
        int h = t - 64;
        float x = hns[h];
        __nv_bfloat16 hb = __float2bfloat16(x);
        float hf = __bfloat162float(hb);
        __nv_bfloat16 lb = __float2bfloat16(x - hf);
        int p = v >> 1, par = v & 1;
        u16* q = (u16*)d_Bfrag;
        q[(p * 64 + h) * 4 + par]     = *(u16*)&hb;
        q[(p * 64 + h) * 4 + 2 + par] = *(u16*)&lb;
    }
}

// ---------------------------------------------------------------------------
// Kernel 2: one batch per block, 256 threads = 8 warps.
// match-hist (overlaps prep via PDL) -> grid-dep sync -> R13 MMA + epilogue.
// ---------------------------------------------------------------------------
#define BPAD 68

struct FinalSmem {
    int sub[8][V];          // 4096 B
    u64 Bf[64 * BPAD];      // 34816 B
    float skeys[S][BPAD];   // 17408 B
    float cs[V];
    float sq[H];
    float ssim[S];
    float sattn[S];
    float sctx[H];
    float sout[V];
    float wA[2], wB2[2], wC[2];
};

__global__ void __launch_bounds__(256, 2) final_kernel(
        const int* __restrict__ seq,
        const float* __restrict__ slot_keys,
        const float* __restrict__ out_w,
        const float* __restrict__ out_b,
        float* __restrict__ out) {
    extern __shared__ char smraw[];
    FinalSmem& sm = *(FinalSmem*)smraw;

    int b = blockIdx.x;
    int t = threadIdx.x;
    int lane = t & 31;
    int warp = t >> 5;
    int gid = lane >> 2;
    int tig = lane & 3;

    const int wm = warp & 3;
    const int wn = warp >> 2;
    const int row0 = wm * 16 + gid;

    int qi = seq[b * L + (L - 1)];

    // ---- match-based histogram: count ALL 4096 tokens, subtract qi later ----
    {
        int* mysub = sm.sub[warp];
#pragma unroll
        for (int i = lane; i < V; i += 32) mysub[i] = 0;
        __syncwarp();

        const int4* s4 = (const int4*)(seq + b * L);
#pragma unroll
        for (int r = 0; r < 4; r++) {
            int4 x = s4[r * 256 + t];
            int toks[4] = {x.x, x.y, x.z, x.w};
#pragma unroll
            for (int c = 0; c < 4; c++) {
                int tok = toks[c];
                u32 mask = __match_any_sync(0xffffffffu, tok);
                if ((mask & ((1u << lane) - 1u)) == 0)
                    mysub[tok] += __popc(mask);
            }
        }
    }

    // slot_keys prefetch (input, independent of prep)
    float2 sk0[4], sk1[4];
#pragma unroll
    for (int nt = 0; nt < 4; nt++) {
        int col = (wn * 4 + nt) * 8 + tig * 2;
        sk0[nt] = *(const float2*)&slot_keys[row0 * H + col];
        sk1[nt] = *(const float2*)&slot_keys[(row0 + 8) * H + col];
    }

    // ---- wait for prep outputs (d_hn, d_gTf, d_Bfrag) ----
    cudaGridDependencySynchronize();

    // Bf copy + q load (prep outputs now visible)
#pragma unroll
    for (int i = t; i < 2048; i += 256) {
        int idx = 2 * i;
        int p = idx >> 6, h = idx & 63;
        ulonglong2 w2v = *(const ulonglong2*)&d_Bfrag[p * 64 + h];
        *(ulonglong2*)&sm.Bf[p * BPAD + h] = w2v;
    }
    if (t < H) sm.sq[t] = d_hn[qi * H + t];
    __syncthreads();  // hist + Bf visible

    if (t < V) {
        int tot = 0;
#pragma unroll
        for (int k = 0; k < 8; k++) tot += sm.sub[k][t];
        if (t == qi) tot -= 1;   // last token excluded from hw
        sm.cs[t] = (float)tot;
    }
    __syncthreads();

    // ---- MMA: A' in regs (pipelined gTf loads), B via padded LDS ----
    float acc[4][4];
#pragma unroll
    for (int nt = 0; nt < 4; nt++)
#pragma unroll
        for (int i = 0; i < 4; i++) acc[nt][i] = 0.0f;

    const float* gr0 = d_gTf + row0 * V;
    const float* gr8 = d_gTf + (row0 + 8) * V;

    float2 g0, g1, g2, g3;
    {
        int v0 = 2 * tig, v1 = v0 + 8;
        g0 = *(const float2*)&gr0[v0];
        g1 = *(const float2*)&gr8[v0];
        g2 = *(const float2*)&gr0[v1];
        g3 = *(const float2*)&gr8[v1];
    }
#pragma unroll
    for (int kt = 0; kt < 8; kt++) {
        int pb = kt * 8 + tig;
        int v0 = 2 * pb, v1 = v0 + 8;
        float2 c0 = *(const float2*)&sm.cs[v0];
        float2 c1 = *(const float2*)&sm.cs[v1];
        float p0x = g0.x * c0.x, p0y = g0.y * c0.y;
        float p1x = g1.x * c0.x, p1y = g1.y * c0.y;
        float p2x = g2.x * c1.x, p2y = g2.y * c1.y;
        float p3x = g3.x * c1.x, p3y = g3.y * c1.y;
        if (kt + 1 < 8) {
            int nv0 = v0 + 16, nv1 = v1 + 16;
            g0 = *(const float2*)&gr0[nv0];
            g1 = *(const float2*)&gr8[nv0];
            g2 = *(const float2*)&gr0[nv1];
            g3 = *(const float2*)&gr8[nv1];
        }
        u32 aH0 = pack_bf16x2(p0x, p0y);
        u32 aH1 = pack_bf16x2(p1x, p1y);
        u32 aH2 = pack_bf16x2(p2x, p2y);
        u32 aH3 = pack_bf16x2(p3x, p3y);
        u32 aL0 = pack_bf16x2(p0x - bflo(aH0), p0y - bfhi(aH0));
        u32 aL1 = pack_bf16x2(p1x - bflo(aH1), p1y - bfhi(aH1));
        u32 aL2 = pack_bf16x2(p2x - bflo(aH2), p2y - bfhi(aH2));
        u32 aL3 = pack_bf16x2(p3x - bflo(aH3), p3y - bfhi(aH3));
#pragma unroll
        for (int nt = 0; nt < 4; nt++) {
            int h = (wn * 4 + nt) * 8 + gid;
            u64 B0 = sm.Bf[pb * BPAD + h];
            u64 B1 = sm.Bf[(pb + 4) * BPAD + h];
            u32 bH0 = (u32)B0, bL0 = (u32)(B0 >> 32);
            u32 bH1 = (u32)B1, bL1 = (u32)(B1 >> 32);
            mma_bf16(acc[nt], aH0, aH1, aH2, aH3, bH0, bH1);
            mma_bf16(acc[nt], aH0, aH1, aH2, aH3, bL0, bL1);
            mma_bf16(acc[nt], aL0, aL1, aL2, aL3, bH0, bH1);
        }
    }

    // keys (+ prefetched slot_keys) -> shared
#pragma unroll
    for (int nt = 0; nt < 4; nt++) {
        int col = (wn * 4 + nt) * 8 + tig * 2;
        sm.skeys[row0][col]         = acc[nt][0] + sk0[nt].x;
        sm.skeys[row0][col + 1]     = acc[nt][1] + sk0[nt].y;
        sm.skeys[row0 + 8][col]     = acc[nt][2] + sk1[nt].x;
        sm.skeys[row0 + 8][col + 1] = acc[nt][3] + sk1[nt].y;
    }

    // q norm (warps 0,1)
    if (t < H) {
        float qv = sm.sq[t];
        float s = qv * qv;
#pragma unroll
        for (int off = 16; off > 0; off >>= 1)
            s += __shfl_xor_sync(0xffffffffu, s, off);
        if (lane == 0) sm.wA[warp] = s;
    }
    __syncthreads();

    // sim: all 8 warps, slot = warp*8+gid, 4-lane h-split
    {
        float qinv = rsqrtf(fmaxf(sm.wA[0] + sm.wA[1], 1e-24f));
        int slot = warp * 8 + gid;
        const float* row = sm.skeys[slot];
        int base = tig * 16;
        float dot = 0.0f, nk = 0.0f;
#pragma unroll
        for (int i = 0; i < 4; i++) {
            float4 kv = *(const float4*)&row[base + 4 * i];
            float4 qv = *(const float4*)&sm.sq[base + 4 * i];
            dot = fmaf(kv.x, qv.x, dot); nk = fmaf(kv.x, kv.x, nk);
            dot = fmaf(kv.y, qv.y, dot); nk = fmaf(kv.y, kv.y, nk);
            dot = fmaf(kv.z, qv.z, dot); nk = fmaf(kv.z, kv.z, nk);
            dot = fmaf(kv.w, qv.w, dot); nk = fmaf(kv.w, kv.w, nk);
        }
        dot += __shfl_xor_sync(0xffffffffu, dot, 1);
        dot += __shfl_xor_sync(0xffffffffu, dot, 2);
        nk  += __shfl_xor_sync(0xffffffffu, nk, 1);
        nk  += __shfl_xor_sync(0xffffffffu, nk, 2);
        if (tig == 0)
            sm.ssim[slot] = dot * qinv / fmaxf(sqrtf(nk), 1e-12f);
    }
    __syncthreads();

    // softmax over 64 (warps 0,1)
    float simv = 0.0f;
    if (t < S) {
        simv = sm.ssim[t];
        float m = simv;
#pragma unroll
        for (int off = 16; off > 0; off >>= 1)
            m = fmaxf(m, __shfl_xor_sync(0xffffffffu, m, off));
        if (lane == 0) sm.wB2[warp] = m;
    }
    __syncthreads();
    float ev = 0.0f;
    if (t < S) {
        float m = fmaxf(sm.wB2[0], sm.wB2[1]);
        ev = expf(simv - m);
        float s = ev;
#pragma unroll
        for (int off = 16; off > 0; off >>= 1)
            s += __shfl_xor_sync(0xffffffffu, s, off);
        if (lane == 0) sm.wC[warp] = s;
    }
    __syncthreads();
    if (t < S) sm.sattn[t] = ev / (sm.wC[0] + sm.wC[1]);
    __syncthreads();

    // ctx: h = t>>2, 4-lane n-split
    {
        int h = t >> 2, sub = t & 3;
        float c = 0.0f;
#pragma unroll
        for (int i = 0; i < 16; i++) {
            int n = sub * 16 + i;
            c = fmaf(sm.sattn[n], sm.skeys[n][h], c);
        }
        c += __shfl_xor_sync(0xffffffffu, c, 1);
        c += __shfl_xor_sync(0xffffffffu, c, 2);
        if (sub == 0) sm.sctx[h] = c;
    }
    __syncthreads();

    // out GEMV: j = t&127, 2-way k-split via smem combine
    {
        int j = t & 127;
        int kh = (t >> 7) * 32;
        float o = 0.0f;
#pragma unroll
        for (int i = 0; i < 32; i++)
            o = fmaf(sm.sctx[kh + i], out_w[(kh + i) * V + j], o);
        if (t >= 128) sm.sout[j] = o;
        __syncthreads();
        if (t < 128) out[b * V + j] = o + sm.sout[j] + out_b[j];
    }
}

// ---------------------------------------------------------------------------
extern "C" void kernel_launch(void* const* d_in, const int* in_sizes, int n_in,
                              void* d_out, int out_size) {
    const int*   seq       = (const int*)d_in[0];
    const float* embed_w   = (const float*)d_in[1];
    const float* w1        = (const float*)d_in[2];
    const float* b1        = (const float*)d_in[3];
    const float* w2        = (const float*)d_in[4];
    const float* b2        = (const float*)d_in[5];
    const float* ln_g      = (const float*)d_in[6];
    const float* ln_b      = (const float*)d_in[7];
    const float* slot_keys = (const float*)d_in[8];
    // d_in[9] = slot_vals (unused: reference sets vals = keys)
    const float* gate_w    = (const float*)d_in[10];
    const float* gate_b    = (const float*)d_in[11];
    const float* out_w     = (const float*)d_in[12];
    const float* out_b     = (const float*)d_in[13];
    float* out = (float*)d_out;

    int smem_bytes = (int)sizeof(FinalSmem);
    cudaFuncSetAttribute(final_kernel,
                         cudaFuncAttributeMaxDynamicSharedMemorySize, smem_bytes);

    prep_kernel<<<V, 128>>>(embed_w, w1, b1, w2, b2, ln_g, ln_b, gate_w, gate_b);

    // Final launched with programmatic dependent launch: starts during prep,
    // gates on cudaGridDependencySynchronize() before touching prep outputs.
    cudaLaunchConfig_t cfg = {};
    cfg.gridDim = dim3(BATCH, 1, 1);
    cfg.blockDim = dim3(256, 1, 1);
    cfg.dynamicSmemBytes = (size_t)smem_bytes;
    cfg.stream = 0;
    cudaLaunchAttribute attrs[1];
    attrs[0].id = cudaLaunchAttributeProgrammaticStreamSerialization;
    attrs[0].val.programmaticStreamSerializationAllowed = 1;
    cfg.attrs = attrs;
    cfg.numAttrs = 1;
    cudaLaunchKernelEx(&cfg, final_kernel, seq, slot_keys, out_w, out_b, out);
}

// round 16
// speedup vs baseline: 1.2962x; 1.2962x over previous
#include <cuda_runtime.h>
#include <cuda_bf16.h>
#include <cstdint>

#define H 64
#define V 128
#define S 64
#define BATCH 256
#define L 4096

typedef unsigned long long u64;
typedef unsigned int u32;
typedef unsigned short u16;

// Scratch (no allocs allowed)
__device__ float d_hn[V * H];      // LN'd hidden per vocab id
__device__ float d_gTf[S * V];     // gate softmax, transposed [s][v], fp32
__device__ u64   d_Bfrag[64 * 64]; // [p=vpair][h]: lo32 = bf16x2 hi-parts, hi32 = lo

__device__ __forceinline__ u32 pack_bf16x2(float lo, float hi) {
    u32 d;
    asm("cvt.rn.bf16x2.f32 %0, %1, %2;" : "=r"(d) : "f"(hi), "f"(lo));
    return d;
}
__device__ __forceinline__ float bflo(u32 p) { return __uint_as_float(p << 16); }
__device__ __forceinline__ float bfhi(u32 p) { return __uint_as_float(p & 0xFFFF0000u); }

__device__ __forceinline__ void mma_bf16(float* c, u32 a0, u32 a1, u32 a2, u32 a3,
                                         u32 b0, u32 b1) {
    asm volatile(
        "mma.sync.aligned.m16n8k16.row.col.f32.bf16.bf16.f32 "
        "{%0,%1,%2,%3}, {%4,%5,%6,%7}, {%8,%9}, {%0,%1,%2,%3};"
        : "+f"(c[0]), "+f"(c[1]), "+f"(c[2]), "+f"(c[3])
        : "r"(a0), "r"(a1), "r"(a2), "r"(a3), "r"(b0), "r"(b1));
}

// ---------------------------------------------------------------------------
// Kernel 1: per-vocab precompute ONLY (R13-proven). grid = 128, 128 threads.
// ---------------------------------------------------------------------------
__global__ void __launch_bounds__(128) prep_kernel(
        const float* __restrict__ embed_w,
        const float* __restrict__ w1,
        const float* __restrict__ b1,
        const float* __restrict__ w2,
        const float* __restrict__ b2,
        const float* __restrict__ ln_g,
        const float* __restrict__ ln_b,
        const float* __restrict__ gate_w,
        const float* __restrict__ gate_b) {
    int t = threadIdx.x;
    int lane = t & 31;
    int warp = t >> 5;
    int v = blockIdx.x;

    __shared__ float hs[H];
    __shared__ float us[2 * H];
    __shared__ float hns[H];
    __shared__ float wred[2][2];

    if (t < H) hs[t] = embed_w[v * H + t];
    __syncthreads();

    {
        float a0 = b1[t], a1 = 0.0f;
#pragma unroll
        for (int k = 0; k < H; k += 2) {
            a0 = fmaf(hs[k],     w1[k * (2 * H) + t],       a0);
            a1 = fmaf(hs[k + 1], w1[(k + 1) * (2 * H) + t], a1);
        }
        us[t] = fmaxf(a0 + a1, 0.0f);
    }
    __syncthreads();

    float xval = 0.0f;
    if (t < H) {
        float a0 = b2[t], a1 = 0.0f;
#pragma unroll
        for (int k = 0; k < 2 * H; k += 2) {
            a0 = fmaf(us[k],     w2[k * H + t],       a0);
            a1 = fmaf(us[k + 1], w2[(k + 1) * H + t], a1);
        }
        xval = hs[t] + a0 + a1;
        float s = xval, sq = xval * xval;
#pragma unroll
        for (int off = 16; off > 0; off >>= 1) {
            s  += __shfl_xor_sync(0xffffffffu, s, off);
            sq += __shfl_xor_sync(0xffffffffu, sq, off);
        }
        if (lane == 0) { wred[warp][0] = s; wred[warp][1] = sq; }
    }
    __syncthreads();

    if (t < H) {
        float s  = wred[0][0] + wred[1][0];
        float sq = wred[0][1] + wred[1][1];
        float mu = s * (1.0f / H);
        float var = sq * (1.0f / H) - mu * mu;
        float rstd = rsqrtf(var + 1e-5f);
        float val = (xval - mu) * rstd * ln_g[t] + ln_b[t];
        hns[t] = val;
        d_hn[v * H + t] = val;
    }
    __syncthreads();

    float l = 0.0f;
    if (t < S) {
        float a0 = gate_b[t], a1 = 0.0f;
#pragma unroll
        for (int k = 0; k < H; k += 2) {
            a0 = fmaf(hns[k],     gate_w[k * S + t],       a0);
            a1 = fmaf(hns[k + 1], gate_w[(k + 1) * S + t], a1);
        }
        l = a0 + a1;
        float m = l;
#pragma unroll
        for (int off = 16; off > 0; off >>= 1)
            m = fmaxf(m, __shfl_xor_sync(0xffffffffu, m, off));
        if (lane == 0) wred[warp][0] = m;
    }
    __syncthreads();

    float ev = 0.0f;
    if (t < S) {
        float m = fmaxf(wred[0][0], wred[1][0]);
        ev = expf(l - m);
        float ssum = ev;
#pragma unroll
        for (int off = 16; off > 0; off >>= 1)
            ssum += __shfl_xor_sync(0xffffffffu, ssum, off);
        if (lane == 0) wred[warp][1] = ssum;
    }
    __syncthreads();

    if (t < S) {
        d_gTf[t * V + v] = ev / (wred[0][1] + wred[1][1]);
    } else {
        int h = t - 64;
        float x = hns[h];
        __nv_bfloat16 hb = __float2bfloat16(x);
        float hf = __bfloat162float(hb);
        __nv_bfloat16 lb = __float2bfloat16(x - hf);
        int p = v >> 1, par = v & 1;
        u16* q = (u16*)d_Bfrag;
        q[(p * 64 + h) * 4 + par]     = *(u16*)&hb;
        q[(p * 64 + h) * 4 + 2 + par] = *(u16*)&lb;
    }
}

// ---------------------------------------------------------------------------
// Kernel 2: one batch per block, 256 threads = 8 warps.
// MLP-4 hist -> R13 MMA (depth-2 gate pipeline) -> R13 epilogue.
// ---------------------------------------------------------------------------
#define BPAD 68

struct FinalSmem {
    int sub[8][V];          // 4096 B
    u64 Bf[64 * BPAD];      // 34816 B
    float skeys[S][BPAD];   // 17408 B
    float cs[V];
    float sq[H];
    float ssim[S];
    float sattn[S];
    float sctx[H];
    float sout[V];
    float wA[2], wB2[2], wC[2];
};

__global__ void __launch_bounds__(256, 2) final_kernel(
        const int* __restrict__ seq,
        const float* __restrict__ slot_keys,
        const float* __restrict__ out_w,
        const float* __restrict__ out_b,
        float* __restrict__ out) {
    extern __shared__ char smraw[];
    FinalSmem& sm = *(FinalSmem*)smraw;

    int b = blockIdx.x;
    int t = threadIdx.x;
    int lane = t & 31;
    int warp = t >> 5;
    int gid = lane >> 2;
    int tig = lane & 3;

    const int wm = warp & 3;
    const int wn = warp >> 2;
    const int row0 = wm * 16 + gid;

    int qi = seq[b * L + (L - 1)];

    // ---- hist: 4 upfront int4 loads (MLP=4), count ALL 4096 tokens ----
    {
        const int4* s4 = (const int4*)(seq + b * L);
        int4 x0 = s4[t];
        int4 x1 = s4[t + 256];
        int4 x2 = s4[t + 512];
        int4 x3 = s4[t + 768];

        int* mysub = sm.sub[warp];
#pragma unroll
        for (int i = lane; i < V; i += 32) mysub[i] = 0;
        __syncwarp();

        atomicAdd(&mysub[x0.x], 1); atomicAdd(&mysub[x0.y], 1);
        atomicAdd(&mysub[x0.z], 1); atomicAdd(&mysub[x0.w], 1);
        atomicAdd(&mysub[x1.x], 1); atomicAdd(&mysub[x1.y], 1);
        atomicAdd(&mysub[x1.z], 1); atomicAdd(&mysub[x1.w], 1);
        atomicAdd(&mysub[x2.x], 1); atomicAdd(&mysub[x2.y], 1);
        atomicAdd(&mysub[x2.z], 1); atomicAdd(&mysub[x2.w], 1);
        atomicAdd(&mysub[x3.x], 1); atomicAdd(&mysub[x3.y], 1);
        atomicAdd(&mysub[x3.z], 1); atomicAdd(&mysub[x3.w], 1);
    }

    // Bf copy + sq + slot_keys prefetch (independent of hist)
#pragma unroll
    for (int i = t; i < 2048; i += 256) {
        int idx = 2 * i;
        int p = idx >> 6, h = idx & 63;
        ulonglong2 w2v = *(const ulonglong2*)&d_Bfrag[p * 64 + h];
        *(ulonglong2*)&sm.Bf[p * BPAD + h] = w2v;
    }
    if (t < H) sm.sq[t] = d_hn[qi * H + t];

    float2 sk0[4], sk1[4];
#pragma unroll
    for (int nt = 0; nt < 4; nt++) {
        int col = (wn * 4 + nt) * 8 + tig * 2;
        sk0[nt] = *(const float2*)&slot_keys[row0 * H + col];
        sk1[nt] = *(const float2*)&slot_keys[(row0 + 8) * H + col];
    }
    __syncthreads();  // B1: hist subs + Bf complete

    if (t < V) {
        int tot = 0;
#pragma unroll
        for (int k = 0; k < 8; k++) tot += sm.sub[k][t];
        if (t == qi) tot -= 1;   // exclude the last token (hw = seq[:, :-1])
        sm.cs[t] = (float)tot;
    }
    __syncthreads();  // B2

    // ---- MMA: A' in regs (depth-2 pipelined gTf loads), B via padded LDS ----
    float acc[4][4];
#pragma unroll
    for (int nt = 0; nt < 4; nt++)
#pragma unroll
        for (int i = 0; i < 4; i++) acc[nt][i] = 0.0f;

    const float* gr0 = d_gTf + row0 * V;
    const float* gr8 = d_gTf + (row0 + 8) * V;

    float2 g0[2], g1[2], g2[2], g3[2];
#pragma unroll
    for (int st = 0; st < 2; st++) {
        int pb = st * 8 + tig;
        int v0 = 2 * pb, v1 = v0 + 8;
        g0[st] = *(const float2*)&gr0[v0];
        g1[st] = *(const float2*)&gr8[v0];
        g2[st] = *(const float2*)&gr0[v1];
        g3[st] = *(const float2*)&gr8[v1];
    }
#pragma unroll
    for (int kt = 0; kt < 8; kt++) {
        int cur = kt & 1;
        int pb = kt * 8 + tig;
        int v0 = 2 * pb, v1 = v0 + 8;
        float2 c0 = *(const float2*)&sm.cs[v0];
        float2 c1 = *(const float2*)&sm.cs[v1];
        float p0x = g0[cur].x * c0.x, p0y = g0[cur].y * c0.y;
        float p1x = g1[cur].x * c0.x, p1y = g1[cur].y * c0.y;
        float p2x = g2[cur].x * c1.x, p2y = g2[cur].y * c1.y;
        float p3x = g3[cur].x * c1.x, p3y = g3[cur].y * c1.y;
        if (kt + 2 < 8) {
            int npb = (kt + 2) * 8 + tig;
            int nv0 = 2 * npb, nv1 = nv0 + 8;
            g0[cur] = *(const float2*)&gr0[nv0];
            g1[cur] = *(const float2*)&gr8[nv0];
            g2[cur] = *(const float2*)&gr0[nv1];
            g3[cur] = *(const float2*)&gr8[nv1];
        }
        u32 aH0 = pack_bf16x2(p0x, p0y);
        u32 aH1 = pack_bf16x2(p1x, p1y);
        u32 aH2 = pack_bf16x2(p2x, p2y);
        u32 aH3 = pack_bf16x2(p3x, p3y);
        u32 aL0 = pack_bf16x2(p0x - bflo(aH0), p0y - bfhi(aH0));
        u32 aL1 = pack_bf16x2(p1x - bflo(aH1), p1y - bfhi(aH1));
        u32 aL2 = pack_bf16x2(p2x - bflo(aH2), p2y - bfhi(aH2));
        u32 aL3 = pack_bf16x2(p3x - bflo(aH3), p3y - bfhi(aH3));
#pragma unroll
        for (int nt = 0; nt < 4; nt++) {
            int h = (wn * 4 + nt) * 8 + gid;
            u64 B0 = sm.Bf[pb * BPAD + h];
            u64 B1 = sm.Bf[(pb + 4) * BPAD + h];
            u32 bH0 = (u32)B0, bL0 = (u32)(B0 >> 32);
            u32 bH1 = (u32)B1, bL1 = (u32)(B1 >> 32);
            mma_bf16(acc[nt], aH0, aH1, aH2, aH3, bH0, bH1);
            mma_bf16(acc[nt], aH0, aH1, aH2, aH3, bL0, bL1);
            mma_bf16(acc[nt], aL0, aL1, aL2, aL3, bH0, bH1);
        }
    }

    // keys (+ prefetched slot_keys) -> shared
#pragma unroll
    for (int nt = 0; nt < 4; nt++) {
        int col = (wn * 4 + nt) * 8 + tig * 2;
        sm.skeys[row0][col]         = acc[nt][0] + sk0[nt].x;
        sm.skeys[row0][col + 1]     = acc[nt][1] + sk0[nt].y;
        sm.skeys[row0 + 8][col]     = acc[nt][2] + sk1[nt].x;
        sm.skeys[row0 + 8][col + 1] = acc[nt][3] + sk1[nt].y;
    }

    // q norm (warps 0,1)
    if (t < H) {
        float qv = sm.sq[t];
        float s = qv * qv;
#pragma unroll
        for (int off = 16; off > 0; off >>= 1)
            s += __shfl_xor_sync(0xffffffffu, s, off);
        if (lane == 0) sm.wA[warp] = s;
    }
    __syncthreads();

    // sim: all 8 warps, slot = warp*8+gid, 4-lane h-split
    {
        float qinv = rsqrtf(fmaxf(sm.wA[0] + sm.wA[1], 1e-24f));
        int slot = warp * 8 + gid;
        const float* row = sm.skeys[slot];
        int base = tig * 16;
        float dot = 0.0f, nk = 0.0f;
#pragma unroll
        for (int i = 0; i < 4; i++) {
            float4 kv = *(const float4*)&row[base + 4 * i];
            float4 qv = *(const float4*)&sm.sq[base + 4 * i];
            dot = fmaf(kv.x, qv.x, dot); nk = fmaf(kv.x, kv.x, nk);
            dot = fmaf(kv.y, qv.y, dot); nk = fmaf(kv.y, kv.y, nk);
            dot = fmaf(kv.z, qv.z, dot); nk = fmaf(kv.z, kv.z, nk);
            dot = fmaf(kv.w, qv.w, dot); nk = fmaf(kv.w, kv.w, nk);
        }
        dot += __shfl_xor_sync(0xffffffffu, dot, 1);
        dot += __shfl_xor_sync(0xffffffffu, dot, 2);
        nk  += __shfl_xor_sync(0xffffffffu, nk, 1);
        nk  += __shfl_xor_sync(0xffffffffu, nk, 2);
        if (tig == 0)
            sm.ssim[slot] = dot * qinv / fmaxf(sqrtf(nk), 1e-12f);
    }
    __syncthreads();

    // softmax over 64 (warps 0,1)
    float simv = 0.0f;
    if (t < S) {
        simv = sm.ssim[t];
        float m = simv;
#pragma unroll
        for (int off = 16; off > 0; off >>= 1)
            m = fmaxf(m, __shfl_xor_sync(0xffffffffu, m, off));
        if (lane == 0) sm.wB2[warp] = m;
    }
    __syncthreads();
    float ev = 0.0f;
    if (t < S) {
        float m = fmaxf(sm.wB2[0], sm.wB2[1]);
        ev = expf(simv - m);
        float s = ev;
#pragma unroll
        for (int off = 16; off > 0; off >>= 1)
            s += __shfl_xor_sync(0xffffffffu, s, off);
        if (lane == 0) sm.wC[warp] = s;
    }
    __syncthreads();
    if (t < S) sm.sattn[t] = ev / (sm.wC[0] + sm.wC[1]);
    __syncthreads();

    // ctx: h = t>>2, 4-lane n-split
    {
        int h = t >> 2, sub = t & 3;
        float c = 0.0f;
#pragma unroll
        for (int i = 0; i < 16; i++) {
            int n = sub * 16 + i;
            c = fmaf(sm.sattn[n], sm.skeys[n][h], c);
        }
        c += __shfl_xor_sync(0xffffffffu, c, 1);
        c += __shfl_xor_sync(0xffffffffu, c, 2);
        if (sub == 0) sm.sctx[h] = c;
    }
    __syncthreads();

    // out GEMV: j = t&127, 2-way k-split via smem combine
    {
        int j = t & 127;
        int kh = (t >> 7) * 32;
        float o = 0.0f;
#pragma unroll
        for (int i = 0; i < 32; i++)
            o = fmaf(sm.sctx[kh + i], out_w[(kh + i) * V + j], o);
        if (t >= 128) sm.sout[j] = o;
        __syncthreads();
        if (t < 128) out[b * V + j] = o + sm.sout[j] + out_b[j];
    }
}

// ---------------------------------------------------------------------------
extern "C" void kernel_launch(void* const* d_in, const int* in_sizes, int n_in,
                              void* d_out, int out_size) {
    const int*   seq       = (const int*)d_in[0];
    const float* embed_w   = (const float*)d_in[1];
    const float* w1        = (const float*)d_in[2];
    const float* b1        = (const float*)d_in[3];
    const float* w2        = (const float*)d_in[4];
    const float* b2        = (const float*)d_in[5];
    const float* ln_g      = (const float*)d_in[6];
    const float* ln_b      = (const float*)d_in[7];
    const float* slot_keys = (const float*)d_in[8];
    // d_in[9] = slot_vals (unused: reference sets vals = keys)
    const float* gate_w    = (const float*)d_in[10];
    const float* gate_b    = (const float*)d_in[11];
    const float* out_w     = (const float*)d_in[12];
    const float* out_b     = (const float*)d_in[13];
    float* out = (float*)d_out;

    int smem_bytes = (int)sizeof(FinalSmem);
    cudaFuncSetAttribute(final_kernel,
                         cudaFuncAttributeMaxDynamicSharedMemorySize, smem_bytes);

    prep_kernel<<<V, 128>>>(embed_w, w1, b1, w2, b2, ln_g, ln_b, gate_w, gate_b);
    final_kernel<<<BATCH, 256, smem_bytes>>>(seq, slot_keys, out_w, out_b, out);
}